// round 11
// baseline (speedup 1.0000x reference)
#include <cuda_runtime.h>
#include <cstdint>

#define B_ 16
#define D_ 256
#define N_ 8192
#define R_ 16
#define K_ 2048

__device__ float          g_val[B_ * R_ * N_];
__device__ unsigned short g_idx16[B_ * R_ * K_];

__device__ __forceinline__ unsigned int f2mono(float f) {
    unsigned int u = __float_as_uint(f);
    return (u & 0x80000000u) ? ~u : (u | 0x80000000u);
}

// ---------------------------------------------------------------------------
// Kernel 1: val[b,r,n] = sum_d x[b,d,n]*W[r,d] + bias[r].
// Accumulation order decoded via R10 unequal-count probe: SPLIT-K = 2 —
// two contiguous 128-halves, each sequential FMA from zero (ascending d),
// combined with one add, bias added last.
// ---------------------------------------------------------------------------
__global__ void __launch_bounds__(512) k_proj(const float* __restrict__ x,
                                              const float* __restrict__ W,
                                              const float* __restrict__ bias,
                                              float* __restrict__ out_idxsort) {
    __shared__ float Ws[R_ * D_];
    __shared__ float vs[R_][33];
    const int tid = threadIdx.x;
    for (int i = tid; i < R_ * D_; i += 512) Ws[i] = W[i];
    __syncthreads();

    const int bb   = blockIdx.x >> 8;
    const int nblk = blockIdx.x & 255;
    const int lane = tid & 31;
    const int r    = tid >> 5;
    const int n    = nblk * 32 + lane;

    const float* xp = x + (size_t)bb * D_ * N_ + n;
    const float* wr = Ws + r * D_;

    float q0 = 0.0f, q1 = 0.0f;
#pragma unroll 8
    for (int d = 0; d < 128; d++)
        q0 = fmaf(xp[(size_t)d * N_], wr[d], q0);
#pragma unroll 8
    for (int d = 128; d < 256; d++)
        q1 = fmaf(xp[(size_t)d * N_], wr[d], q1);

    const float v = __fadd_rn(__fadd_rn(q0, q1), bias[r]);

    g_val[((size_t)(bb * R_ + r)) * N_ + n] = v;
    vs[r][lane] = v;
    __syncthreads();

    if (r == 0) {
        float best = vs[0][lane];
        int   br   = 0;
#pragma unroll
        for (int rr = 1; rr < R_; rr++) {
            float t = vs[rr][lane];
            if (t > best) { best = t; br = rr; }    // first max (jax argmax)
        }
        out_idxsort[(size_t)bb * N_ + n] = (float)br;
    }
}

// ---------------------------------------------------------------------------
// Kernel 2: per (b,r) row, bitonic sort of 8192 packed u64 keys
// (value descending; exact ties -> LOWER index first).
// ---------------------------------------------------------------------------
__global__ void __launch_bounds__(1024) k_sort(float* __restrict__ out_idxstar) {
    extern __shared__ unsigned long long skey[];
    const int tid = threadIdx.x;
    const int bb  = blockIdx.x >> 4;
    const int r   = blockIdx.x & 15;

    const float* vp = g_val + ((size_t)(bb * R_ + r)) * N_;
    for (int i = tid; i < N_; i += 1024) {
        skey[i] = ((unsigned long long)f2mono(vp[i]) << 32) |
                  (unsigned int)(N_ - 1 - i);      // tie -> lower index first
    }
    __syncthreads();

    for (int size = 2; size <= N_; size <<= 1) {
        for (int stride = size >> 1; stride > 0; stride >>= 1) {
            for (int i = tid; i < N_; i += 1024) {
                int j = i ^ stride;
                if (j > i) {
                    unsigned long long a = skey[i], b = skey[j];
                    bool up = ((i & size) == 0);
                    if (up ? (a < b) : (a > b)) { skey[i] = b; skey[j] = a; }
                }
            }
            __syncthreads();
        }
    }

    for (int i = tid; i < K_; i += 1024) {
        int idx = N_ - 1 - (int)(skey[i] & 0xFFFFFFFFu);
        g_idx16[(bb * R_ + r) * K_ + i] = (unsigned short)idx;
        float fidx = (float)idx;
#pragma unroll
        for (int j = 0; j < R_; j++)
            out_idxstar[(((size_t)(bb * R_ + j)) * R_ + r) * K_ + i] = fidx;
    }
}

// ---------------------------------------------------------------------------
// Kernel 3: FEAT_star[b,d,r,k] = x[b,d, idx_top[b,r,k]].
// ---------------------------------------------------------------------------
__global__ void __launch_bounds__(256) k_gather(const float* __restrict__ x,
                                                float* __restrict__ out_feat) {
    __shared__ float row[N_];
    const int tid = threadIdx.x;
    const int bb  = blockIdx.x >> 8;
    const int d   = blockIdx.x & 255;

    const float4* xp4  = (const float4*)(x + ((size_t)(bb * D_ + d)) * N_);
    float4*       row4 = (float4*)row;
    for (int i = tid; i < N_ / 4; i += 256) row4[i] = xp4[i];
    __syncthreads();

    const ushort4* ip = (const ushort4*)(g_idx16 + (size_t)bb * R_ * K_);
    float4*        op = (float4*)(out_feat + ((size_t)(bb * D_ + d)) * R_ * K_);
    for (int t = tid; t < (R_ * K_) / 4; t += 256) {
        ushort4 i4 = ip[t];
        float4 v;
        v.x = row[i4.x];
        v.y = row[i4.y];
        v.z = row[i4.z];
        v.w = row[i4.w];
        op[t] = v;
    }
}

// ---------------------------------------------------------------------------
extern "C" void kernel_launch(void* const* d_in, const int* in_sizes, int n_in,
                              void* d_out, int out_size) {
    (void)in_sizes; (void)n_in; (void)out_size;
    const float* x    = (const float*)d_in[0];
    const float* W    = (const float*)d_in[1];
    const float* bias = (const float*)d_in[2];

    float* out       = (float*)d_out;
    float* out_feat  = out;
    float* out_istar = out + (size_t)B_ * D_ * R_ * K_;
    float* out_isort = out_istar + (size_t)B_ * R_ * R_ * K_;

    k_proj<<<B_ * 256, 512>>>(x, W, bias, out_isort);

    cudaFuncSetAttribute(k_sort, cudaFuncAttributeMaxDynamicSharedMemorySize, N_ * 8);
    k_sort<<<B_ * R_, 1024, N_ * 8>>>(out_istar);

    k_gather<<<B_ * D_, 256>>>(x, out_feat);
}

// round 12
// speedup vs baseline: 1.1068x; 1.1068x over previous
#include <cuda_runtime.h>
#include <cstdint>

#define B_ 16
#define D_ 256
#define N_ 8192
#define R_ 16
#define K_ 2048

__device__ float          g_val[B_ * R_ * N_];
__device__ unsigned short g_idx16[B_ * R_ * K_];

__device__ __forceinline__ unsigned int f2mono(float f) {
    unsigned int u = __float_as_uint(f);
    return (u & 0x80000000u) ? ~u : (u | 0x80000000u);
}

// ---------------------------------------------------------------------------
// Kernel 1: val[b,r,n] = sum_d x[b,d,n]*W[r,d] + bias[r]  (split-K=2 exact:
// q0 = FMA-sequential d=0..127 from zero, q1 = d=128..255, v=(q0+q1)+bias).
// Register tiling: thread owns 2 n (tid, tid+256) x 16 r (two groups of 8).
// One x LDG feeds 32 FMAs. Argmax over r carried in registers.
// ---------------------------------------------------------------------------
__global__ void __launch_bounds__(256) k_proj(const float* __restrict__ x,
                                              const float* __restrict__ W,
                                              const float* __restrict__ bias,
                                              float* __restrict__ out_idxsort) {
    __shared__ float Ws[R_ * D_];
    __shared__ float bs[R_];
    const int tid = threadIdx.x;
    for (int i = tid; i < R_ * D_; i += 256) Ws[i] = W[i];
    if (tid < R_) bs[tid] = bias[tid];
    __syncthreads();

    const int bb    = blockIdx.x >> 4;          // 16 blocks per batch
    const int nb    = blockIdx.x & 15;
    const int nbase = nb * 512;
    const float* xp = x + (size_t)bb * D_ * N_ + nbase + tid;

    float best[2] = {-3.402823466e+38f, -3.402823466e+38f};
    int   bidx[2] = {0, 0};

#pragma unroll
    for (int rg = 0; rg < 2; rg++) {
        float a0[2][8], a1[2][8];
#pragma unroll
        for (int u = 0; u < 2; u++)
#pragma unroll
            for (int r8 = 0; r8 < 8; r8++) { a0[u][r8] = 0.0f; a1[u][r8] = 0.0f; }

        const float* wg = Ws + (rg * 8) * D_;

#pragma unroll 4
        for (int d = 0; d < 128; d++) {
            const float xv0 = xp[(size_t)d * N_];
            const float xv1 = xp[(size_t)d * N_ + 256];
#pragma unroll
            for (int r8 = 0; r8 < 8; r8++) {
                const float w = wg[r8 * D_ + d];
                a0[0][r8] = fmaf(xv0, w, a0[0][r8]);
                a0[1][r8] = fmaf(xv1, w, a0[1][r8]);
            }
        }
#pragma unroll 4
        for (int d = 128; d < 256; d++) {
            const float xv0 = xp[(size_t)d * N_];
            const float xv1 = xp[(size_t)d * N_ + 256];
#pragma unroll
            for (int r8 = 0; r8 < 8; r8++) {
                const float w = wg[r8 * D_ + d];
                a1[0][r8] = fmaf(xv0, w, a1[0][r8]);
                a1[1][r8] = fmaf(xv1, w, a1[1][r8]);
            }
        }

#pragma unroll
        for (int u = 0; u < 2; u++)
#pragma unroll
            for (int r8 = 0; r8 < 8; r8++) {
                const int   r = rg * 8 + r8;
                const float v = __fadd_rn(__fadd_rn(a0[u][r8], a1[u][r8]), bs[r]);
                g_val[((size_t)(bb * R_ + r)) * N_ + nbase + tid + u * 256] = v;
                if (v > best[u]) { best[u] = v; bidx[u] = r; }  // first max kept
            }
    }

#pragma unroll
    for (int u = 0; u < 2; u++)
        out_idxsort[(size_t)bb * N_ + nbase + tid + u * 256] = (float)bidx[u];
}

// ---------------------------------------------------------------------------
// Kernel 2: per (b,r) row, bitonic sort of 8192 packed u64 keys
// (value descending; exact ties -> LOWER index first).
// ---------------------------------------------------------------------------
__global__ void __launch_bounds__(1024) k_sort(float* __restrict__ out_idxstar) {
    extern __shared__ unsigned long long skey[];
    const int tid = threadIdx.x;
    const int bb  = blockIdx.x >> 4;
    const int r   = blockIdx.x & 15;

    const float* vp = g_val + ((size_t)(bb * R_ + r)) * N_;
    for (int i = tid; i < N_; i += 1024) {
        skey[i] = ((unsigned long long)f2mono(vp[i]) << 32) |
                  (unsigned int)(N_ - 1 - i);      // tie -> lower index first
    }
    __syncthreads();

    for (int size = 2; size <= N_; size <<= 1) {
        for (int stride = size >> 1; stride > 0; stride >>= 1) {
            for (int i = tid; i < N_; i += 1024) {
                int j = i ^ stride;
                if (j > i) {
                    unsigned long long a = skey[i], b = skey[j];
                    bool up = ((i & size) == 0);
                    if (up ? (a < b) : (a > b)) { skey[i] = b; skey[j] = a; }
                }
            }
            __syncthreads();
        }
    }

    for (int i = tid; i < K_; i += 1024) {
        int idx = N_ - 1 - (int)(skey[i] & 0xFFFFFFFFu);
        g_idx16[(bb * R_ + r) * K_ + i] = (unsigned short)idx;
        float fidx = (float)idx;
#pragma unroll
        for (int j = 0; j < R_; j++)
            out_idxstar[(((size_t)(bb * R_ + j)) * R_ + r) * K_ + i] = fidx;
    }
}

// ---------------------------------------------------------------------------
// Kernel 3: FEAT_star[b,d,r,k] = x[b,d, idx_top[b,r,k]].
// ---------------------------------------------------------------------------
__global__ void __launch_bounds__(256) k_gather(const float* __restrict__ x,
                                                float* __restrict__ out_feat) {
    __shared__ float row[N_];
    const int tid = threadIdx.x;
    const int bb  = blockIdx.x >> 8;
    const int d   = blockIdx.x & 255;

    const float4* xp4  = (const float4*)(x + ((size_t)(bb * D_ + d)) * N_);
    float4*       row4 = (float4*)row;
    for (int i = tid; i < N_ / 4; i += 256) row4[i] = xp4[i];
    __syncthreads();

    const ushort4* ip = (const ushort4*)(g_idx16 + (size_t)bb * R_ * K_);
    float4*        op = (float4*)(out_feat + ((size_t)(bb * D_ + d)) * R_ * K_);
    for (int t = tid; t < (R_ * K_) / 4; t += 256) {
        ushort4 i4 = ip[t];
        float4 v;
        v.x = row[i4.x];
        v.y = row[i4.y];
        v.z = row[i4.z];
        v.w = row[i4.w];
        op[t] = v;
    }
}

// ---------------------------------------------------------------------------
extern "C" void kernel_launch(void* const* d_in, const int* in_sizes, int n_in,
                              void* d_out, int out_size) {
    (void)in_sizes; (void)n_in; (void)out_size;
    const float* x    = (const float*)d_in[0];
    const float* W    = (const float*)d_in[1];
    const float* bias = (const float*)d_in[2];

    float* out       = (float*)d_out;
    float* out_feat  = out;
    float* out_istar = out + (size_t)B_ * D_ * R_ * K_;
    float* out_isort = out_istar + (size_t)B_ * R_ * R_ * K_;

    k_proj<<<B_ * 16, 256>>>(x, W, bias, out_isort);

    cudaFuncSetAttribute(k_sort, cudaFuncAttributeMaxDynamicSharedMemorySize, N_ * 8);
    k_sort<<<B_ * R_, 1024, N_ * 8>>>(out_istar);

    k_gather<<<B_ * D_, 256>>>(x, out_feat);
}

// round 13
// speedup vs baseline: 1.2326x; 1.1136x over previous
#include <cuda_runtime.h>
#include <cstdint>

#define B_ 16
#define D_ 256
#define N_ 8192
#define R_ 16
#define K_ 2048

__device__ float          g_val[B_ * R_ * N_];
__device__ unsigned short g_idx16[B_ * R_ * K_];

__device__ __forceinline__ unsigned int f2mono(float f) {
    unsigned int u = __float_as_uint(f);
    return (u & 0x80000000u) ? ~u : (u | 0x80000000u);
}

// ---------------------------------------------------------------------------
// Kernel 1: val[b,r,n] = sum_d x[b,d,n]*W[r,d] + bias[r]  (bit-exact split-K=2:
// q0 = seq FMA d=0..127 from zero, q1 = d=128..255, v = (q0+q1)+bias).
// 1 n per thread, all 16 r in registers; W via float4 LDS. grid = B*32.
// ---------------------------------------------------------------------------
__global__ void __launch_bounds__(256) k_proj(const float* __restrict__ x,
                                              const float* __restrict__ W,
                                              const float* __restrict__ bias,
                                              float* __restrict__ out_idxsort) {
    __shared__ float Ws[R_ * D_];
    __shared__ float bs[R_];
    const int tid = threadIdx.x;
    for (int i = tid; i < R_ * D_; i += 256) Ws[i] = W[i];
    if (tid < R_) bs[tid] = bias[tid];
    __syncthreads();

    const int bb = blockIdx.x >> 5;          // 32 blocks per batch
    const int nb = blockIdx.x & 31;
    const int n  = nb * 256 + tid;
    const float* xp = x + (size_t)bb * D_ * N_ + n;

    float a0[R_], a1[R_];
#pragma unroll
    for (int r = 0; r < R_; r++) { a0[r] = 0.0f; a1[r] = 0.0f; }

#pragma unroll 2
    for (int d = 0; d < 128; d += 4) {
        float xv[4];
#pragma unroll
        for (int q = 0; q < 4; q++) xv[q] = xp[(size_t)(d + q) * N_];
#pragma unroll
        for (int r = 0; r < R_; r++) {
            const float4 w4 = *(const float4*)(Ws + r * D_ + d);
            a0[r] = fmaf(xv[0], w4.x, a0[r]);
            a0[r] = fmaf(xv[1], w4.y, a0[r]);
            a0[r] = fmaf(xv[2], w4.z, a0[r]);
            a0[r] = fmaf(xv[3], w4.w, a0[r]);
        }
    }
#pragma unroll 2
    for (int d = 128; d < 256; d += 4) {
        float xv[4];
#pragma unroll
        for (int q = 0; q < 4; q++) xv[q] = xp[(size_t)(d + q) * N_];
#pragma unroll
        for (int r = 0; r < R_; r++) {
            const float4 w4 = *(const float4*)(Ws + r * D_ + d);
            a1[r] = fmaf(xv[0], w4.x, a1[r]);
            a1[r] = fmaf(xv[1], w4.y, a1[r]);
            a1[r] = fmaf(xv[2], w4.z, a1[r]);
            a1[r] = fmaf(xv[3], w4.w, a1[r]);
        }
    }

    float best = -3.402823466e+38f;
    int   bidx = 0;
#pragma unroll
    for (int r = 0; r < R_; r++) {
        const float v = __fadd_rn(__fadd_rn(a0[r], a1[r]), bs[r]);
        g_val[((size_t)(bb * R_ + r)) * N_ + n] = v;
        if (v > best) { best = v; bidx = r; }       // first max kept
    }
    out_idxsort[(size_t)bb * N_ + n] = (float)bidx;
}

// ---------------------------------------------------------------------------
// Kernel 2: per (b,r): radix-select the 2048th-largest u64 key (8 MSB rounds),
// compact keys >= T (exactly 2048, keys distinct), bitonic-sort the 2048.
// Key = f2mono(val)<<32 | (N-1-i)  -> ties: lower index first.
// ---------------------------------------------------------------------------
__global__ void __launch_bounds__(1024) k_sort(float* __restrict__ out_idxstar) {
    extern __shared__ unsigned long long sm[];
    unsigned long long* skey  = sm;          // 8192
    unsigned long long* csort = sm + N_;     // 2048
    __shared__ unsigned int hist[256];
    __shared__ unsigned int suf[256];
    __shared__ unsigned int s_rem, s_cnt;
    __shared__ unsigned long long s_prefix;

    const int tid  = threadIdx.x;
    const int lane = tid & 31;
    const int bb   = blockIdx.x >> 4;
    const int r    = blockIdx.x & 15;

    const float* vp = g_val + ((size_t)(bb * R_ + r)) * N_;
    for (int i = tid; i < N_; i += 1024)
        skey[i] = ((unsigned long long)f2mono(vp[i]) << 32) |
                  (unsigned int)(N_ - 1 - i);
    if (tid == 0) { s_rem = K_; s_cnt = 0; s_prefix = 0ull; }
    __syncthreads();

    // ---- 8-round MSB radix select of the K_-th largest key ----
#pragma unroll
    for (int round = 0; round < 8; round++) {
        const int shift = 56 - 8 * round;
        if (tid < 256) hist[tid] = 0;
        __syncthreads();
        const unsigned long long pref = s_prefix;

        for (int i = tid; i < N_; i += 1024) {
            const unsigned long long key = skey[i];
            const bool act = (round == 0) || ((key >> (shift + 8)) == pref);
            const unsigned am = __ballot_sync(0xffffffffu, act);
            if (act) {
                const int bin = (int)((key >> shift) & 255);
                const unsigned mask = __match_any_sync(am, bin);
                if (lane == __ffs(mask) - 1)
                    atomicAdd(&hist[bin], __popc(mask));
            }
        }
        __syncthreads();

        // suffix sums: suf[i] = sum hist[i..255]
        if (tid < 256) suf[tid] = hist[tid];
        __syncthreads();
        for (int off = 1; off < 256; off <<= 1) {
            unsigned add = 0;
            if (tid < 256 && tid + off < 256) add = suf[tid + off];
            __syncthreads();
            if (tid < 256) suf[tid] += add;
            __syncthreads();
        }
        const unsigned rem = s_rem;
        __syncthreads();
        if (tid < 256) {
            const unsigned hi = (tid == 255) ? 0u : suf[tid + 1];
            if (rem > hi && rem <= suf[tid]) {      // unique winning bin
                s_rem    = rem - hi;
                s_prefix = (pref << 8) | (unsigned)tid;
            }
        }
        __syncthreads();
    }
    const unsigned long long T = s_prefix;   // exact 2048th-largest key

    // ---- compact keys >= T (warp-aggregated) ----
    for (int i = tid; i < N_; i += 1024) {
        const unsigned long long key = skey[i];
        const bool take = (key >= T);
        const unsigned m = __ballot_sync(0xffffffffu, take);
        if (m) {
            unsigned base = 0;
            if (lane == __ffs(m) - 1) base = atomicAdd(&s_cnt, __popc(m));
            base = __shfl_sync(0xffffffffu, base, __ffs(m) - 1);
            if (take)
                csort[base + __popc(m & ((1u << lane) - 1u))] = key;
        }
    }
    __syncthreads();

    // ---- bitonic sort the 2048 survivors, descending ----
    for (int size = 2; size <= K_; size <<= 1) {
        for (int stride = size >> 1; stride > 0; stride >>= 1) {
            for (int i = tid; i < K_; i += 1024) {
                const int j = i ^ stride;
                if (j > i) {
                    unsigned long long a = csort[i], b = csort[j];
                    const bool up = ((i & size) == 0);
                    if (up ? (a < b) : (a > b)) { csort[i] = b; csort[j] = a; }
                }
            }
            __syncthreads();
        }
    }

    // ---- emit top-k indices + idx_star ----
    for (int i = tid; i < K_; i += 1024) {
        const int idx = N_ - 1 - (int)(csort[i] & 0xFFFFFFFFu);
        g_idx16[(bb * R_ + r) * K_ + i] = (unsigned short)idx;
        const float fidx = (float)idx;
#pragma unroll
        for (int j = 0; j < R_; j++)
            out_idxstar[(((size_t)(bb * R_ + j)) * R_ + r) * K_ + i] = fidx;
    }
}

// ---------------------------------------------------------------------------
// Kernel 3: FEAT_star[b,d,r,k] = x[b,d, idx_top[b,r,k]].
// ---------------------------------------------------------------------------
__global__ void __launch_bounds__(256) k_gather(const float* __restrict__ x,
                                                float* __restrict__ out_feat) {
    __shared__ float row[N_];
    const int tid = threadIdx.x;
    const int bb  = blockIdx.x >> 8;
    const int d   = blockIdx.x & 255;

    const float4* xp4  = (const float4*)(x + ((size_t)(bb * D_ + d)) * N_);
    float4*       row4 = (float4*)row;
    for (int i = tid; i < N_ / 4; i += 256) row4[i] = xp4[i];
    __syncthreads();

    const ushort4* ip = (const ushort4*)(g_idx16 + (size_t)bb * R_ * K_);
    float4*        op = (float4*)(out_feat + ((size_t)(bb * D_ + d)) * R_ * K_);
    for (int t = tid; t < (R_ * K_) / 4; t += 256) {
        ushort4 i4 = ip[t];
        float4 v;
        v.x = row[i4.x];
        v.y = row[i4.y];
        v.z = row[i4.z];
        v.w = row[i4.w];
        op[t] = v;
    }
}

// ---------------------------------------------------------------------------
extern "C" void kernel_launch(void* const* d_in, const int* in_sizes, int n_in,
                              void* d_out, int out_size) {
    (void)in_sizes; (void)n_in; (void)out_size;
    const float* x    = (const float*)d_in[0];
    const float* W    = (const float*)d_in[1];
    const float* bias = (const float*)d_in[2];

    float* out       = (float*)d_out;
    float* out_feat  = out;
    float* out_istar = out + (size_t)B_ * D_ * R_ * K_;
    float* out_isort = out_istar + (size_t)B_ * R_ * R_ * K_;

    k_proj<<<B_ * 32, 256>>>(x, W, bias, out_isort);

    const int sort_smem = (N_ + K_) * 8;   // 80 KB
    cudaFuncSetAttribute(k_sort, cudaFuncAttributeMaxDynamicSharedMemorySize, sort_smem);
    k_sort<<<B_ * R_, 1024, sort_smem>>>(out_istar);

    k_gather<<<B_ * D_, 256>>>(x, out_feat);
}

// round 16
// speedup vs baseline: 1.6882x; 1.3696x over previous
#include <cuda_runtime.h>
#include <cstdint>

#define B_ 16
#define D_ 256
#define N_ 8192
#define R_ 16
#define K_ 2048

__device__ float          g_val[B_ * R_ * N_];
__device__ unsigned short g_idx16[B_ * R_ * K_];

__device__ __forceinline__ unsigned int f2mono(float f) {
    unsigned int u = __float_as_uint(f);
    return (u & 0x80000000u) ? ~u : (u | 0x80000000u);
}

// ---------------------------------------------------------------------------
// Kernel 1: val[b,r,n] = sum_d x*W + bias  (bit-exact split-K=2).
// q0 half parked in private smem slot to halve live accumulator registers.
// ---------------------------------------------------------------------------
__global__ void __launch_bounds__(256) k_proj(const float* __restrict__ x,
                                              const float* __restrict__ W,
                                              const float* __restrict__ bias,
                                              float* __restrict__ out_idxsort) {
    __shared__ float Ws[R_ * D_];
    __shared__ float bs[R_];
    __shared__ float q0s[R_][256];
    const int tid = threadIdx.x;
    for (int i = tid; i < R_ * D_; i += 256) Ws[i] = W[i];
    if (tid < R_) bs[tid] = bias[tid];
    __syncthreads();

    const int bb = blockIdx.x >> 5;
    const int nb = blockIdx.x & 31;
    const int n  = nb * 256 + tid;
    const float* xp = x + (size_t)bb * D_ * N_ + n;

    float a[R_];
#pragma unroll
    for (int r = 0; r < R_; r++) a[r] = 0.0f;

    // ---- first K-half: d = 0..127, sequential FMA from zero ----
    for (int d = 0; d < 128; d += 8) {
        float xv[8];
#pragma unroll
        for (int q = 0; q < 8; q++) xv[q] = xp[(size_t)(d + q) * N_];
#pragma unroll
        for (int r = 0; r < R_; r++) {
            const float4 wa = *(const float4*)(Ws + r * D_ + d);
            const float4 wb = *(const float4*)(Ws + r * D_ + d + 4);
            a[r] = fmaf(xv[0], wa.x, a[r]);
            a[r] = fmaf(xv[1], wa.y, a[r]);
            a[r] = fmaf(xv[2], wa.z, a[r]);
            a[r] = fmaf(xv[3], wa.w, a[r]);
            a[r] = fmaf(xv[4], wb.x, a[r]);
            a[r] = fmaf(xv[5], wb.y, a[r]);
            a[r] = fmaf(xv[6], wb.z, a[r]);
            a[r] = fmaf(xv[7], wb.w, a[r]);
        }
    }
#pragma unroll
    for (int r = 0; r < R_; r++) { q0s[r][tid] = a[r]; a[r] = 0.0f; }

    // ---- second K-half: d = 128..255 ----
    for (int d = 128; d < 256; d += 8) {
        float xv[8];
#pragma unroll
        for (int q = 0; q < 8; q++) xv[q] = xp[(size_t)(d + q) * N_];
#pragma unroll
        for (int r = 0; r < R_; r++) {
            const float4 wa = *(const float4*)(Ws + r * D_ + d);
            const float4 wb = *(const float4*)(Ws + r * D_ + d + 4);
            a[r] = fmaf(xv[0], wa.x, a[r]);
            a[r] = fmaf(xv[1], wa.y, a[r]);
            a[r] = fmaf(xv[2], wa.z, a[r]);
            a[r] = fmaf(xv[3], wa.w, a[r]);
            a[r] = fmaf(xv[4], wb.x, a[r]);
            a[r] = fmaf(xv[5], wb.y, a[r]);
            a[r] = fmaf(xv[6], wb.z, a[r]);
            a[r] = fmaf(xv[7], wb.w, a[r]);
        }
    }

    float best = -3.402823466e+38f;
    int   bidx = 0;
#pragma unroll
    for (int r = 0; r < R_; r++) {
        const float v = __fadd_rn(__fadd_rn(q0s[r][tid], a[r]), bs[r]);
        g_val[((size_t)(bb * R_ + r)) * N_ + n] = v;
        if (v > best) { best = v; bidx = r; }       // first max kept
    }
    out_idxsort[(size_t)bb * N_ + n] = (float)bidx;
}

// ---------------------------------------------------------------------------
// Kernel 2: per (b,r): 4-round radix select on the 32-bit mono value,
// exact boundary-tie resolution, compaction to exactly 2048 keys,
// bitonic sort, emit.
// ---------------------------------------------------------------------------
__global__ void __launch_bounds__(1024) k_sort(float* __restrict__ out_idxstar) {
    extern __shared__ unsigned int sm[];
    unsigned int*       smono = sm;                               // 8192 u32
    unsigned long long* csort = (unsigned long long*)(sm + N_);   // 2048 u64
    __shared__ unsigned int hist[256];
    __shared__ unsigned int suf[257];
    __shared__ unsigned int Lm[1024];
    __shared__ unsigned int s_rem, s_cnt, s_bcnt, s_prefix;

    const int tid  = threadIdx.x;
    const int lane = tid & 31;
    const int bb   = blockIdx.x >> 4;
    const int r    = blockIdx.x & 15;

    const float* vp = g_val + ((size_t)(bb * R_ + r)) * N_;
    for (int i = tid; i < N_; i += 1024) smono[i] = f2mono(vp[i]);
    if (tid == 0) { s_rem = K_; s_cnt = 0; s_bcnt = 0; s_prefix = 0; suf[256] = 0; }
    __syncthreads();

    // ---- 4-round MSB radix select on mono ----
#pragma unroll
    for (int round = 0; round < 4; round++) {
        const int shift = 24 - 8 * round;
        if (tid < 256) hist[tid] = 0;
        __syncthreads();
        const unsigned pref = s_prefix;

        for (int i = tid; i < N_; i += 1024) {
            const unsigned mono = smono[i];
            const bool act = (round == 0) || ((mono >> (shift + 8)) == pref);
            const unsigned am = __ballot_sync(0xffffffffu, act);
            if (act) {
                const int bin = (int)((mono >> shift) & 255u);
                const unsigned mask = __match_any_sync(am, bin);
                if (lane == __ffs(mask) - 1) atomicAdd(&hist[bin], __popc(mask));
            }
        }
        __syncthreads();

        // warp-0 suffix scan of hist into suf (no block syncs inside)
        if (tid < 32) {
            unsigned v[8], s[8];
#pragma unroll
            for (int k = 0; k < 8; k++) v[k] = hist[tid * 8 + k];
            unsigned run = 0;
#pragma unroll
            for (int k = 7; k >= 0; k--) { run += v[k]; s[k] = run; }
            unsigned acc = run;
#pragma unroll
            for (int off = 1; off < 32; off <<= 1) {
                const unsigned t = __shfl_down_sync(0xffffffffu, acc, off);
                if (tid + off < 32) acc += t;
            }
            const unsigned higher = acc - run;     // sum over lanes > tid
#pragma unroll
            for (int k = 0; k < 8; k++) suf[tid * 8 + k] = s[k] + higher;
        }
        __syncthreads();

        const unsigned rem = s_rem;
        __syncthreads();   // RACE FIX: all threads must read s_rem before the
                           // winning thread overwrites it below (R14 bug).
        if (tid < 256) {
            const unsigned hi = suf[tid + 1];
            if (rem > hi && rem <= suf[tid]) {     // unique winning bin
                s_rem    = rem - hi;
                s_prefix = (pref << 8) | (unsigned)tid;
            }
        }
        __syncthreads();
    }
    const unsigned T = s_prefix;   // mono value of the 2048th-largest element
    const unsigned m = s_rem;      // how many to take from the == T class

    // ---- compact: mono > T  -> csort ; mono == T -> boundary list ----
    for (int i = tid; i < N_; i += 1024) {
        const unsigned mono = smono[i];
        const bool take = (mono > T);
        const unsigned mk = __ballot_sync(0xffffffffu, take);
        if (mk) {
            unsigned base = 0;
            if (lane == __ffs(mk) - 1) base = atomicAdd(&s_cnt, __popc(mk));
            base = __shfl_sync(0xffffffffu, base, __ffs(mk) - 1);
            if (take) {
                const unsigned pos = base + __popc(mk & ((1u << lane) - 1u));
                if (pos < K_)      // guard: never taken in a correct run
                    csort[pos] = ((unsigned long long)mono << 32) |
                                 (unsigned)(N_ - 1 - i);
            }
        }
        if (mono == T) {
            const unsigned p = atomicAdd(&s_bcnt, 1u);
            if (p < 1024) Lm[p] = (unsigned)(N_ - 1 - i);
        }
    }
    __syncthreads();

    // ---- boundary: take the m entries with LARGEST low word (lowest index) ----
    const unsigned c2 = (s_bcnt < 1024u) ? s_bcnt : 1024u;
    for (unsigned e = tid; e < c2; e += 1024) {
        const unsigned lw = Lm[e];
        unsigned rank = 0;
        for (unsigned j = 0; j < c2; j++) rank += (Lm[j] > lw) ? 1u : 0u;
        if (rank < m) {
            const unsigned pos = atomicAdd(&s_cnt, 1u);
            if (pos < K_)          // guard: never taken in a correct run
                csort[pos] = ((unsigned long long)T << 32) | lw;
        }
    }
    __syncthreads();   // s_cnt == 2048 now

    // ---- bitonic sort the 2048 survivors, descending ----
    for (int size = 2; size <= K_; size <<= 1) {
        for (int stride = size >> 1; stride > 0; stride >>= 1) {
            for (int i = tid; i < K_; i += 1024) {
                const int j = i ^ stride;
                if (j > i) {
                    unsigned long long a = csort[i], b = csort[j];
                    const bool up = ((i & size) == 0);
                    if (up ? (a < b) : (a > b)) { csort[i] = b; csort[j] = a; }
                }
            }
            __syncthreads();
        }
    }

    // ---- emit ----
    for (int i = tid; i < K_; i += 1024) {
        const int idx = N_ - 1 - (int)(csort[i] & 0xFFFFFFFFu);
        g_idx16[(bb * R_ + r) * K_ + i] = (unsigned short)idx;
        const float fidx = (float)idx;
#pragma unroll
        for (int j = 0; j < R_; j++)
            out_idxstar[(((size_t)(bb * R_ + j)) * R_ + r) * K_ + i] = fidx;
    }
}

// ---------------------------------------------------------------------------
// Kernel 3: FEAT_star[b,d,r,k] = x[b,d, idx_top[b,r,k]].
// ---------------------------------------------------------------------------
__global__ void __launch_bounds__(256) k_gather(const float* __restrict__ x,
                                                float* __restrict__ out_feat) {
    __shared__ float row[N_];
    const int tid = threadIdx.x;
    const int bb  = blockIdx.x >> 8;
    const int d   = blockIdx.x & 255;

    const float4* xp4  = (const float4*)(x + ((size_t)(bb * D_ + d)) * N_);
    float4*       row4 = (float4*)row;
    for (int i = tid; i < N_ / 4; i += 256) row4[i] = xp4[i];
    __syncthreads();

    const ushort4* ip = (const ushort4*)(g_idx16 + (size_t)bb * R_ * K_);
    float4*        op = (float4*)(out_feat + ((size_t)(bb * D_ + d)) * R_ * K_);
    for (int t = tid; t < (R_ * K_) / 4; t += 256) {
        ushort4 i4 = ip[t];
        float4 v;
        v.x = row[i4.x];
        v.y = row[i4.y];
        v.z = row[i4.z];
        v.w = row[i4.w];
        op[t] = v;
    }
}

// ---------------------------------------------------------------------------
extern "C" void kernel_launch(void* const* d_in, const int* in_sizes, int n_in,
                              void* d_out, int out_size) {
    (void)in_sizes; (void)n_in; (void)out_size;
    const float* x    = (const float*)d_in[0];
    const float* W    = (const float*)d_in[1];
    const float* bias = (const float*)d_in[2];

    float* out       = (float*)d_out;
    float* out_feat  = out;
    float* out_istar = out + (size_t)B_ * D_ * R_ * K_;
    float* out_isort = out_istar + (size_t)B_ * R_ * R_ * K_;

    k_proj<<<B_ * 32, 256>>>(x, W, bias, out_isort);

    const int sort_smem = N_ * 4 + K_ * 8;   // 48 KB
    cudaFuncSetAttribute(k_sort, cudaFuncAttributeMaxDynamicSharedMemorySize, sort_smem);
    k_sort<<<B_ * R_, 1024, sort_smem>>>(out_istar);

    k_gather<<<B_ * D_, 256>>>(x, out_feat);
}